// round 2
// baseline (speedup 1.0000x reference)
#include <cuda_runtime.h>

#define NB 4
#define NC 64
#define NS 4
#define NM 6
#define NP 21
#define HS 64
#define WS 64
#define HH 256
#define WW 256

// Folded, pre-reduced weights: for segment (u,v), channel c, pair p=(i<=j):
//   g_wfold[(uv*64+c)*21+p] = (mean_o w[u,v,i,j,c,o] + [i<j] mean_o w[u,v,j,i,c,o]) / 4096
__device__ float g_wfold[NS * NS * NC * NP];

__constant__ int c_pi[NP] = {0,0,0,0,0,0, 1,1,1,1,1, 2,2,2,2, 3,3,3, 4,4, 5};
__constant__ int c_pj[NP] = {0,1,2,3,4,5, 1,2,3,4,5, 2,3,4,5, 3,4,5, 4,5, 5};

// grid = 16*21 blocks of 256 threads. Block (uv, p): reduce C_OUT (=64) for all 64 c.
__global__ void prep_weights_kernel(const float* __restrict__ w) {
    int blk = blockIdx.x;
    int uv = blk / NP;
    int p  = blk % NP;
    int i = c_pi[p], j = c_pj[p];
    int warp = threadIdx.x >> 5;
    int lane = threadIdx.x & 31;
    const float* wij = w + (size_t)((uv * NM + i) * NM + j) * (NC * NC);
    const float* wji = w + (size_t)((uv * NM + j) * NM + i) * (NC * NC);
    #pragma unroll
    for (int cc = 0; cc < 8; cc++) {
        int c = warp * 8 + cc;
        const float* b1 = wij + c * NC;
        float s = b1[lane] + b1[lane + 32];
        if (i != j) {
            const float* b2 = wji + c * NC;
            s += b2[lane] + b2[lane + 32];
        }
        #pragma unroll
        for (int off = 16; off; off >>= 1)
            s += __shfl_xor_sync(0xffffffffu, s, off);
        if (lane == 0)
            g_wfold[(uv * NC + c) * NP + p] = s * (1.0f / (64.0f * 4096.0f));
    }
}

// One CTA per (b,c,u,v) segment (64x64 pixels). 256 threads, 16 pixels/thread
// held in registers; min/max pass then Chebyshev-accumulate pass; 21-dot with
// folded weights; tanh; broadcast-store.
__global__ __launch_bounds__(256) void cft_main_kernel(const float* __restrict__ x,
                                                       float* __restrict__ out) {
    int seg = blockIdx.x;              // ((b*64+c)*4+u)*4+v
    int v = seg & 3;
    int u = (seg >> 2) & 3;
    int bc = seg >> 4;
    int c = bc & 63;
    size_t base = (size_t)bc * (HH * WW) + (size_t)u * HS * WW + (size_t)v * WS;
    const float4* __restrict__ xin = (const float4*)(x + base);
    int tid = threadIdx.x;
    int lane = tid & 31, warp = tid >> 5;

    // Load 16 pixels (4 x float4) per thread. q enumerates the 1024 float4s of
    // the segment; row = q>>4 (16 float4 per 64-float row), col = q&15.
    float4 d[4];
    #pragma unroll
    for (int it = 0; it < 4; it++) {
        int q = it * 256 + tid;
        d[it] = xin[(q >> 4) * (WW / 4) + (q & 15)];
    }

    // ---- pass 1: per-segment min/max ----
    float mn = d[0].x, mx = d[0].x;
    #pragma unroll
    for (int it = 0; it < 4; it++) {
        mn = fminf(mn, fminf(fminf(d[it].x, d[it].y), fminf(d[it].z, d[it].w)));
        mx = fmaxf(mx, fmaxf(fmaxf(d[it].x, d[it].y), fmaxf(d[it].z, d[it].w)));
    }
    #pragma unroll
    for (int off = 16; off; off >>= 1) {
        mn = fminf(mn, __shfl_xor_sync(0xffffffffu, mn, off));
        mx = fmaxf(mx, __shfl_xor_sync(0xffffffffu, mx, off));
    }
    __shared__ float s_mn[8], s_mx[8];
    __shared__ float s_acc[8][NP];
    __shared__ float s_sig;
    if (lane == 0) { s_mn[warp] = mn; s_mx[warp] = mx; }
    __syncthreads();
    mn = s_mn[0]; mx = s_mx[0];
    #pragma unroll
    for (int k = 1; k < 8; k++) { mn = fminf(mn, s_mn[k]); mx = fmaxf(mx, s_mx[k]); }

    // ---- pass 2: accumulate the 21 symmetric coeff sums (data in registers) ----
    float a = 2.0f / (mx - mn + 1e-8f);
    float acc[NP];
    #pragma unroll
    for (int k = 0; k < NP; k++) acc[k] = 0.f;

    const float lo = -1.0f + 1e-6f, hi = 1.0f - 1e-6f;
    #pragma unroll
    for (int it = 0; it < 4; it++) {
        float vals[4] = {d[it].x, d[it].y, d[it].z, d[it].w};
        #pragma unroll
        for (int e = 0; e < 4; e++) {
            float xn = fmaf(vals[e] - mn, a, -1.0f);
            float xc = fminf(fmaxf(xn, lo), hi);
            float x2 = xc + xc;
            float T1 = xc;
            float T2 = fmaf(x2, T1, -1.0f);   // cos(k*acos(xc)) == T_k(xc)
            float T3 = fmaf(x2, T2, -T1);
            float T4 = fmaf(x2, T3, -T2);
            float T5 = fmaf(x2, T4, -T3);
            float p1 = xn * T1, p2 = xn * T2, p3 = xn * T3, p4 = xn * T4, p5 = xn * T5;
            acc[0] += xn;
            acc[1] += p1;
            acc[2] += p2;
            acc[3] += p3;
            acc[4] += p4;
            acc[5] += p5;
            acc[6]  = fmaf(p1, T1, acc[6]);
            acc[7]  = fmaf(p1, T2, acc[7]);
            acc[8]  = fmaf(p1, T3, acc[8]);
            acc[9]  = fmaf(p1, T4, acc[9]);
            acc[10] = fmaf(p1, T5, acc[10]);
            acc[11] = fmaf(p2, T2, acc[11]);
            acc[12] = fmaf(p2, T3, acc[12]);
            acc[13] = fmaf(p2, T4, acc[13]);
            acc[14] = fmaf(p2, T5, acc[14]);
            acc[15] = fmaf(p3, T3, acc[15]);
            acc[16] = fmaf(p3, T4, acc[16]);
            acc[17] = fmaf(p3, T5, acc[17]);
            acc[18] = fmaf(p4, T4, acc[18]);
            acc[19] = fmaf(p4, T5, acc[19]);
            acc[20] = fmaf(p5, T5, acc[20]);
        }
    }

    // ---- block-reduce 21 sums ----
    #pragma unroll
    for (int k = 0; k < NP; k++) {
        #pragma unroll
        for (int off = 16; off; off >>= 1)
            acc[k] += __shfl_xor_sync(0xffffffffu, acc[k], off);
    }
    if (lane == 0) {
        #pragma unroll
        for (int k = 0; k < NP; k++) s_acc[warp][k] = acc[k];
    }
    __syncthreads();

    if (tid < 32) {
        float part = 0.f;
        if (tid < NP) {
            float s = 0.f;
            #pragma unroll
            for (int wI = 0; wI < 8; wI++) s += s_acc[wI][tid];
            const float* wf = g_wfold + ((size_t)((u * NS + v) * NC) + c) * NP;
            part = s * wf[tid];
        }
        #pragma unroll
        for (int off = 16; off; off >>= 1)
            part += __shfl_xor_sync(0xffffffffu, part, off);
        if (tid == 0) s_sig = tanhf(part);
    }
    __syncthreads();

    // ---- broadcast-store the segment ----
    float sig = s_sig;
    float4 o4 = make_float4(sig, sig, sig, sig);
    float4* oo = (float4*)(out + base);
    #pragma unroll
    for (int it = 0; it < 4; it++) {
        int q = it * 256 + tid;
        oo[(q >> 4) * (WW / 4) + (q & 15)] = o4;
    }
}

extern "C" void kernel_launch(void* const* d_in, const int* in_sizes, int n_in,
                              void* d_out, int out_size) {
    const float* x = (const float*)d_in[0];
    const float* w = (const float*)d_in[1];
    float* out = (float*)d_out;
    prep_weights_kernel<<<NS * NS * NP, 256>>>(w);
    cft_main_kernel<<<NB * NC * NS * NS, 256>>>(x, out);
}

// round 4
// speedup vs baseline: 1.0925x; 1.0925x over previous
#include <cuda_runtime.h>

#define NB 4
#define NC 64
#define NS 4
#define NM 6
#define NP 21
#define HS 64
#define WS 64
#define HH 256
#define WW 256

// Folded, pre-reduced weights: for segment (u,v), channel c, pair p=(i<=j):
//   g_wfold[(uv*64+c)*21+p] = (mean_o w[u,v,i,j,c,o] + [i<j] mean_o w[u,v,j,i,c,o]) / 4096
__device__ float g_wfold[NS * NS * NC * NP];

__constant__ int c_pi[NP] = {0,0,0,0,0,0, 1,1,1,1,1, 2,2,2,2, 3,3,3, 4,4, 5};
__constant__ int c_pj[NP] = {0,1,2,3,4,5, 1,2,3,4,5, 2,3,4,5, 3,4,5, 4,5, 5};

__global__ void prep_weights_kernel(const float* __restrict__ w) {
    int blk = blockIdx.x;
    int uv = blk / NP;
    int p  = blk % NP;
    int i = c_pi[p], j = c_pj[p];
    int warp = threadIdx.x >> 5;
    int lane = threadIdx.x & 31;
    const float* wij = w + (size_t)((uv * NM + i) * NM + j) * (NC * NC);
    const float* wji = w + (size_t)((uv * NM + j) * NM + i) * (NC * NC);
    #pragma unroll
    for (int cc = 0; cc < 8; cc++) {
        int c = warp * 8 + cc;
        const float* b1 = wij + c * NC;
        float s = b1[lane] + b1[lane + 32];
        if (i != j) {
            const float* b2 = wji + c * NC;
            s += b2[lane] + b2[lane + 32];
        }
        #pragma unroll
        for (int off = 16; off; off >>= 1)
            s += __shfl_xor_sync(0xffffffffu, s, off);
        if (lane == 0)
            g_wfold[(uv * NC + c) * NP + p] = s * (1.0f / (64.0f * 4096.0f));
    }
}

// ---- packed fp32x2 helpers (sm_100+) ----
typedef unsigned long long u64t;

__device__ __forceinline__ u64t pk2(float lo, float hi) {
    u64t r; asm("mov.b64 %0, {%1,%2};" : "=l"(r) : "f"(lo), "f"(hi)); return r;
}
__device__ __forceinline__ void upk2(u64t v, float& lo, float& hi) {
    asm("mov.b64 {%0,%1}, %2;" : "=f"(lo), "=f"(hi) : "l"(v));
}
__device__ __forceinline__ u64t fma2(u64t a, u64t b, u64t c) {
    u64t d; asm("fma.rn.f32x2 %0, %1, %2, %3;" : "=l"(d) : "l"(a), "l"(b), "l"(c)); return d;
}
__device__ __forceinline__ u64t add2(u64t a, u64t b) {
    u64t d; asm("add.rn.f32x2 %0, %1, %2;" : "=l"(d) : "l"(a), "l"(b)); return d;
}
__device__ __forceinline__ u64t sub2(u64t a, u64t b) {
    u64t d; asm("sub.rn.f32x2 %0, %1, %2;" : "=l"(d) : "l"(a), "l"(b)); return d;
}
__device__ __forceinline__ u64t mul2(u64t a, u64t b) {
    u64t d; asm("mul.rn.f32x2 %0, %1, %2;" : "=l"(d) : "l"(a), "l"(b)); return d;
}

// One CTA per (b,c,u,v) segment (64x64 px). 256 threads, 16 px/thread in regs.
// Pass 1: min/max. Pass 2: packed-f32x2 Chebyshev accumulation (8 pixel-pairs).
// 4-round xor reduce (parity classes), 16-partial finisher, tanh, broadcast.
__global__ __launch_bounds__(256, 3) void cft_main_kernel(const float* __restrict__ x,
                                                          float* __restrict__ out) {
    int seg = blockIdx.x;              // ((b*64+c)*4+u)*4+v
    int v = seg & 3;
    int u = (seg >> 2) & 3;
    int bc = seg >> 4;
    int c = bc & 63;
    size_t base = (size_t)bc * (HH * WW) + (size_t)u * HS * WW + (size_t)v * WS;
    const float4* __restrict__ xin = (const float4*)(x + base);
    int tid = threadIdx.x;
    int lane = tid & 31, warp = tid >> 5;

    float4 d[4];
    #pragma unroll
    for (int it = 0; it < 4; it++) {
        int q = it * 256 + tid;
        d[it] = xin[(q >> 4) * (WW / 4) + (q & 15)];
    }

    // ---- pass 1: per-segment min/max ----
    float mn = d[0].x, mx = d[0].x;
    #pragma unroll
    for (int it = 0; it < 4; it++) {
        mn = fminf(mn, fminf(fminf(d[it].x, d[it].y), fminf(d[it].z, d[it].w)));
        mx = fmaxf(mx, fmaxf(fmaxf(d[it].x, d[it].y), fmaxf(d[it].z, d[it].w)));
    }
    #pragma unroll
    for (int off = 16; off; off >>= 1) {
        mn = fminf(mn, __shfl_xor_sync(0xffffffffu, mn, off));
        mx = fmaxf(mx, __shfl_xor_sync(0xffffffffu, mx, off));
    }
    __shared__ float s_mn[8], s_mx[8];
    __shared__ float s_acc[16][NP];
    __shared__ float s_sig;
    if (lane == 0) { s_mn[warp] = mn; s_mx[warp] = mx; }
    __syncthreads();
    mn = s_mn[0]; mx = s_mx[0];
    #pragma unroll
    for (int k = 1; k < 8; k++) { mn = fminf(mn, s_mn[k]); mx = fmaxf(mx, s_mx[k]); }

    // ---- pass 2: packed accumulation of the 21 symmetric coeff sums ----
    float a = 2.0f / (mx - mn + 1e-8f);
    float bb = fmaf(-mn, a, -1.0f);        // xn = x*a + bb
    u64t a2 = pk2(a, a);
    u64t b2 = pk2(bb, bb);
    u64t mone2 = pk2(-1.0f, -1.0f);

    u64t acc[NP];
    #pragma unroll
    for (int k = 0; k < NP; k++) acc[k] = 0ull;   // {+0.0f,+0.0f}

    #pragma unroll
    for (int it = 0; it < 4; it++) {
        #pragma unroll
        for (int half = 0; half < 2; half++) {
            u64t val2 = half ? pk2(d[it].z, d[it].w) : pk2(d[it].x, d[it].y);
            u64t xn = fma2(val2, a2, b2);
            u64t x2 = add2(xn, xn);
            u64t T2 = fma2(x2, xn, mone2);          // T_k(xn): clip dropped (error ~1e-8)
            u64t T3 = sub2(mul2(x2, T2), xn);
            u64t T4 = sub2(mul2(x2, T3), T2);
            u64t T5 = sub2(mul2(x2, T4), T3);
            u64t p1 = mul2(xn, xn);
            u64t p2 = mul2(xn, T2);
            u64t p3 = mul2(xn, T3);
            u64t p4 = mul2(xn, T4);
            u64t p5 = mul2(xn, T5);
            acc[0] = add2(acc[0], xn);
            acc[1] = add2(acc[1], p1);
            acc[2] = add2(acc[2], p2);
            acc[3] = add2(acc[3], p3);
            acc[4] = add2(acc[4], p4);
            acc[5] = add2(acc[5], p5);
            acc[6]  = fma2(p1, xn, acc[6]);   // p1*T1
            acc[7]  = fma2(p1, T2, acc[7]);
            acc[8]  = fma2(p1, T3, acc[8]);
            acc[9]  = fma2(p1, T4, acc[9]);
            acc[10] = fma2(p1, T5, acc[10]);
            acc[11] = fma2(p2, T2, acc[11]);
            acc[12] = fma2(p2, T3, acc[12]);
            acc[13] = fma2(p2, T4, acc[13]);
            acc[14] = fma2(p2, T5, acc[14]);
            acc[15] = fma2(p3, T3, acc[15]);
            acc[16] = fma2(p3, T4, acc[16]);
            acc[17] = fma2(p3, T5, acc[17]);
            acc[18] = fma2(p4, T4, acc[18]);
            acc[19] = fma2(p4, T5, acc[19]);
            acc[20] = fma2(p5, T5, acc[20]);
        }
    }

    // collapse packed halves, then 4 xor rounds (leaves lane-parity partials)
    float as[NP];
    #pragma unroll
    for (int k = 0; k < NP; k++) {
        float lo, hi; upk2(acc[k], lo, hi);
        as[k] = lo + hi;
        #pragma unroll
        for (int off = 16; off >= 2; off >>= 1)
            as[k] += __shfl_xor_sync(0xffffffffu, as[k], off);
    }
    if (lane < 2) {
        #pragma unroll
        for (int k = 0; k < NP; k++) s_acc[warp * 2 + lane][k] = as[k];
    }
    __syncthreads();

    if (tid < 32) {
        float part = 0.f;
        if (tid < NP) {
            float s = 0.f;
            #pragma unroll
            for (int r = 0; r < 16; r++) s += s_acc[r][tid];
            const float* wf = g_wfold + ((size_t)((u * NS + v) * NC) + c) * NP;
            part = s * wf[tid];
        }
        #pragma unroll
        for (int off = 16; off; off >>= 1)
            part += __shfl_xor_sync(0xffffffffu, part, off);
        if (tid == 0) s_sig = tanhf(part);
    }
    __syncthreads();

    // ---- broadcast-store the segment ----
    float sig = s_sig;
    float4 o4 = make_float4(sig, sig, sig, sig);
    float4* oo = (float4*)(out + base);
    #pragma unroll
    for (int it = 0; it < 4; it++) {
        int q = it * 256 + tid;
        oo[(q >> 4) * (WW / 4) + (q & 15)] = o4;
    }
}

extern "C" void kernel_launch(void* const* d_in, const int* in_sizes, int n_in,
                              void* d_out, int out_size) {
    const float* x = (const float*)d_in[0];
    const float* w = (const float*)d_in[1];
    float* out = (float*)d_out;
    prep_weights_kernel<<<NS * NS * NP, 256>>>(w);
    cft_main_kernel<<<NB * NC * NS * NS, 256>>>(x, out);
}

// round 5
// speedup vs baseline: 1.3890x; 1.2714x over previous
#include <cuda_runtime.h>

#define NB 4
#define NC 64
#define NS 4
#define NM 6
#define NP 21
#define HS 64
#define WS 64
#define HH 256
#define WW 256
#define NG 12

// Folded, pre-reduced weights per (u,v,c): 21 symmetric-pair means (incl. /4096)
__device__ float g_wfold[NS * NS * NC * NP];
// Final per-(u,v,c) monomial coefficients g[0..11]: part = sum_px sum_m g_m xn^m
__device__ float g_gcoef[NS * NS * NC * NG];

__constant__ int c_pi[NP] = {0,0,0,0,0,0, 1,1,1,1,1, 2,2,2,2, 3,3,3, 4,4, 5};
__constant__ int c_pj[NP] = {0,1,2,3,4,5, 1,2,3,4,5, 2,3,4,5, 3,4,5, 4,5, 5};

// Monomial coefficients of Chebyshev T_r (row r, column m)
__constant__ float c_cheb[NG][NG] = {
  {1,0,0,0,0,0,0,0,0,0,0,0},
  {0,1,0,0,0,0,0,0,0,0,0,0},
  {-1,0,2,0,0,0,0,0,0,0,0,0},
  {0,-3,0,4,0,0,0,0,0,0,0,0},
  {1,0,-8,0,8,0,0,0,0,0,0,0},
  {0,5,0,-20,0,16,0,0,0,0,0,0},
  {-1,0,18,0,-48,0,32,0,0,0,0,0},
  {0,-7,0,56,0,-112,0,64,0,0,0,0},
  {1,0,-32,0,160,0,-256,0,128,0,0,0},
  {0,9,0,-120,0,432,0,-576,0,256,0,0},
  {-1,0,50,0,-400,0,1120,0,-1280,0,512,0},
  {0,-11,0,220,0,-1232,0,2816,0,-2816,0,1024}
};

// grid = 16*21 blocks of 256 threads: g_wfold[(uv*64+c)*21+p]
__global__ void prep_weights_kernel(const float* __restrict__ w) {
    int blk = blockIdx.x;
    int uv = blk / NP;
    int p  = blk % NP;
    int i = c_pi[p], j = c_pj[p];
    int warp = threadIdx.x >> 5;
    int lane = threadIdx.x & 31;
    const float* wij = w + (size_t)((uv * NM + i) * NM + j) * (NC * NC);
    const float* wji = w + (size_t)((uv * NM + j) * NM + i) * (NC * NC);
    #pragma unroll
    for (int cc = 0; cc < 8; cc++) {
        int c = warp * 8 + cc;
        const float* b1 = wij + c * NC;
        float s = b1[lane] + b1[lane + 32];
        if (i != j) {
            const float* b2 = wji + c * NC;
            s += b2[lane] + b2[lane + 32];
        }
        #pragma unroll
        for (int off = 16; off; off >>= 1)
            s += __shfl_xor_sync(0xffffffffu, s, off);
        if (lane == 0)
            g_wfold[(uv * NC + c) * NP + p] = s * (1.0f / (64.0f * 4096.0f));
    }
}

// 1024 threads: per (uv,c), transform 21 pair-weights -> 12 Chebyshev coeffs h
// (via x*Ti*Tj = (T_{i+j+1}+T_{|i+j-1|}+T_{j-i+1}+T_{|j-i-1|})/4) -> 12 monomial g.
#define ABSI(x) ((x) < 0 ? -(x) : (x))
#define ACCUM(p, i, j) { float wv = wf[p] * 0.25f;              \
    h[(i)+(j)+1] += wv; h[ABSI((i)+(j)-1)] += wv;               \
    h[(j)-(i)+1] += wv; h[ABSI((j)-(i)-1)] += wv; }

__global__ void prep_transform_kernel() {
    int t = blockIdx.x * 256 + threadIdx.x;   // 0..1023 = (uv*64+c)
    if (t >= NS * NS * NC) return;
    const float* wf = g_wfold + (size_t)t * NP;
    float h[NG];
    #pragma unroll
    for (int r = 0; r < NG; r++) h[r] = 0.f;
    ACCUM(0,0,0)  ACCUM(1,0,1)  ACCUM(2,0,2)  ACCUM(3,0,3)  ACCUM(4,0,4)
    ACCUM(5,0,5)  ACCUM(6,1,1)  ACCUM(7,1,2)  ACCUM(8,1,3)  ACCUM(9,1,4)
    ACCUM(10,1,5) ACCUM(11,2,2) ACCUM(12,2,3) ACCUM(13,2,4) ACCUM(14,2,5)
    ACCUM(15,3,3) ACCUM(16,3,4) ACCUM(17,3,5) ACCUM(18,4,4) ACCUM(19,4,5)
    ACCUM(20,5,5)
    #pragma unroll
    for (int m = 0; m < NG; m++) {
        float g = 0.f;
        #pragma unroll
        for (int r = 0; r < NG; r++) g = fmaf(h[r], c_cheb[r][m], g);
        g_gcoef[(size_t)t * NG + m] = g;
    }
}

// ---- packed fp32x2 helpers (sm_100+) ----
typedef unsigned long long u64t;

__device__ __forceinline__ u64t pk2(float lo, float hi) {
    u64t r; asm("mov.b64 %0, {%1,%2};" : "=l"(r) : "f"(lo), "f"(hi)); return r;
}
__device__ __forceinline__ void upk2(u64t v, float& lo, float& hi) {
    asm("mov.b64 {%0,%1}, %2;" : "=f"(lo), "=f"(hi) : "l"(v));
}
__device__ __forceinline__ u64t fma2(u64t a, u64t b, u64t c) {
    u64t d; asm("fma.rn.f32x2 %0, %1, %2, %3;" : "=l"(d) : "l"(a), "l"(b), "l"(c)); return d;
}
__device__ __forceinline__ u64t add2(u64t a, u64t b) {
    u64t d; asm("add.rn.f32x2 %0, %1, %2;" : "=l"(d) : "l"(a), "l"(b)); return d;
}

// One CTA per (b,c,u,v) segment. 256 threads, 16 px/thread in regs.
// Pass 1: min/max. Pass 2: degree-11 Horner on packed pixel pairs, one accumulator.
__global__ __launch_bounds__(256, 4) void cft_main_kernel(const float* __restrict__ x,
                                                          float* __restrict__ out) {
    int seg = blockIdx.x;              // ((b*64+c)*4+u)*4+v
    int v = seg & 3;
    int u = (seg >> 2) & 3;
    int bc = seg >> 4;
    int c = bc & 63;
    size_t base = (size_t)bc * (HH * WW) + (size_t)u * HS * WW + (size_t)v * WS;
    const float4* __restrict__ xin = (const float4*)(x + base);
    int tid = threadIdx.x;
    int lane = tid & 31, warp = tid >> 5;

    float4 d[4];
    #pragma unroll
    for (int it = 0; it < 4; it++) {
        int q = it * 256 + tid;
        d[it] = xin[(q >> 4) * (WW / 4) + (q & 15)];
    }

    // ---- pass 1: per-segment min/max ----
    float mn = d[0].x, mx = d[0].x;
    #pragma unroll
    for (int it = 0; it < 4; it++) {
        mn = fminf(mn, fminf(fminf(d[it].x, d[it].y), fminf(d[it].z, d[it].w)));
        mx = fmaxf(mx, fmaxf(fmaxf(d[it].x, d[it].y), fmaxf(d[it].z, d[it].w)));
    }
    #pragma unroll
    for (int off = 16; off; off >>= 1) {
        mn = fminf(mn, __shfl_xor_sync(0xffffffffu, mn, off));
        mx = fmaxf(mx, __shfl_xor_sync(0xffffffffu, mx, off));
    }
    __shared__ float s_mn[8], s_mx[8];
    __shared__ float s_part[8];
    __shared__ float s_sig;
    if (lane == 0) { s_mn[warp] = mn; s_mx[warp] = mx; }
    __syncthreads();
    mn = s_mn[0]; mx = s_mx[0];
    #pragma unroll
    for (int k = 1; k < 8; k++) { mn = fminf(mn, s_mn[k]); mx = fmaxf(mx, s_mx[k]); }

    // ---- pass 2: packed Horner accumulation ----
    float a = 2.0f / (mx - mn + 1e-8f);
    float bb = fmaf(-mn, a, -1.0f);        // xn = x*a + bb
    u64t a2 = pk2(a, a);
    u64t b2 = pk2(bb, bb);

    const float* __restrict__ gp = g_gcoef + ((size_t)((u * NS + v) * NC) + c) * NG;
    u64t G[NG];
    #pragma unroll
    for (int m = 0; m < NG; m++) { float gm = __ldg(gp + m); G[m] = pk2(gm, gm); }

    u64t acc = 0ull;   // {+0.0f,+0.0f}
    #pragma unroll
    for (int it = 0; it < 4; it++) {
        #pragma unroll
        for (int half = 0; half < 2; half++) {
            u64t val2 = half ? pk2(d[it].z, d[it].w) : pk2(d[it].x, d[it].y);
            u64t xn = fma2(val2, a2, b2);
            u64t p = G[11];
            #pragma unroll
            for (int m = 10; m >= 0; m--) p = fma2(p, xn, G[m]);
            acc = add2(acc, p);
        }
    }

    // ---- reduce one scalar across block ----
    float lo, hi; upk2(acc, lo, hi);
    float part = lo + hi;
    #pragma unroll
    for (int off = 16; off; off >>= 1)
        part += __shfl_xor_sync(0xffffffffu, part, off);
    if (lane == 0) s_part[warp] = part;
    __syncthreads();
    if (tid == 0) {
        float s = s_part[0];
        #pragma unroll
        for (int k = 1; k < 8; k++) s += s_part[k];
        s_sig = tanhf(s);
    }
    __syncthreads();

    // ---- broadcast-store the segment ----
    float sig = s_sig;
    float4 o4 = make_float4(sig, sig, sig, sig);
    float4* oo = (float4*)(out + base);
    #pragma unroll
    for (int it = 0; it < 4; it++) {
        int q = it * 256 + tid;
        oo[(q >> 4) * (WW / 4) + (q & 15)] = o4;
    }
}

extern "C" void kernel_launch(void* const* d_in, const int* in_sizes, int n_in,
                              void* d_out, int out_size) {
    const float* x = (const float*)d_in[0];
    const float* w = (const float*)d_in[1];
    float* out = (float*)d_out;
    prep_weights_kernel<<<NS * NS * NP, 256>>>(w);
    prep_transform_kernel<<<4, 256>>>();
    cft_main_kernel<<<NB * NC * NS * NS, 256>>>(x, out);
}

// round 7
// speedup vs baseline: 1.3901x; 1.0008x over previous
#include <cuda_runtime.h>

#define NB 4
#define NC 64
#define NS 4
#define NM 6
#define NP 21
#define HS 64
#define WS 64
#define HH 256
#define WW 256
#define NG 12
#define NROWS (NS * NS * NM * NM * NC)   // 36864 rows of 64 floats

// Per-row means of w over C_OUT (incl. 1/64/4096): g_wsum[uv][i][j][c]
__device__ float g_wsum[NROWS];
// Final per-(u,v,c) monomial coefficients g[0..11]: part = sum_px sum_m g_m xn^m
__device__ float g_gcoef[NS * NS * NC * NG];

// Monomial coefficients of Chebyshev T_r (row r, column m)
__constant__ float c_cheb[NG][NG] = {
  {1,0,0,0,0,0,0,0,0,0,0,0},
  {0,1,0,0,0,0,0,0,0,0,0,0},
  {-1,0,2,0,0,0,0,0,0,0,0,0},
  {0,-3,0,4,0,0,0,0,0,0,0,0},
  {1,0,-8,0,8,0,0,0,0,0,0,0},
  {0,5,0,-20,0,16,0,0,0,0,0,0},
  {-1,0,18,0,-48,0,32,0,0,0,0,0},
  {0,-7,0,56,0,-112,0,64,0,0,0,0},
  {1,0,-32,0,160,0,-256,0,128,0,0,0},
  {0,9,0,-120,0,432,0,-576,0,256,0,0},
  {-1,0,50,0,-400,0,1120,0,-1280,0,512,0},
  {0,-11,0,220,0,-1232,0,2816,0,-2816,0,1024}
};

// grid = 4608 blocks x 256: one warp per 64-float contiguous row, coalesced.
__global__ void prep_rowsum_kernel(const float* __restrict__ w) {
    int r = blockIdx.x * 8 + (threadIdx.x >> 5);
    int lane = threadIdx.x & 31;
    const float2* row = (const float2*)(w + (size_t)r * 64);
    float2 v2 = __ldg(row + lane);
    float s = v2.x + v2.y;
    #pragma unroll
    for (int off = 16; off; off >>= 1)
        s += __shfl_xor_sync(0xffffffffu, s, off);
    if (lane == 0)
        g_wsum[r] = s * (1.0f / (64.0f * 4096.0f));
}

// 1024 threads: per (uv,c), fold symmetric pairs, expand x*Ti*Tj into Chebyshev
// basis (x*Ti*Tj = (T_{i+j+1}+T_{|i+j-1|}+T_{j-i+1}+T_{|j-i-1|})/4), then
// convert to monomial coefficients g[0..11].
#define ABSI(x) ((x) < 0 ? -(x) : (x))
#define ACCUM(i, j) { float wv = g_wsum[((uv * 36 + (i) * 6 + (j)) << 6) + c];   \
    if ((i) != (j)) wv += g_wsum[((uv * 36 + (j) * 6 + (i)) << 6) + c];          \
    wv *= 0.25f;                                                                  \
    h[(i)+(j)+1] += wv; h[ABSI((i)+(j)-1)] += wv;                                 \
    h[(j)-(i)+1] += wv; h[ABSI((j)-(i)-1)] += wv; }

__global__ void prep_transform_kernel() {
    int t = blockIdx.x * 256 + threadIdx.x;   // 0..1023 = (uv*64+c)
    if (t >= NS * NS * NC) return;
    int uv = t >> 6;
    int c = t & 63;
    float h[NG];
    #pragma unroll
    for (int r = 0; r < NG; r++) h[r] = 0.f;
    ACCUM(0,0) ACCUM(0,1) ACCUM(0,2) ACCUM(0,3) ACCUM(0,4) ACCUM(0,5)
    ACCUM(1,1) ACCUM(1,2) ACCUM(1,3) ACCUM(1,4) ACCUM(1,5)
    ACCUM(2,2) ACCUM(2,3) ACCUM(2,4) ACCUM(2,5)
    ACCUM(3,3) ACCUM(3,4) ACCUM(3,5)
    ACCUM(4,4) ACCUM(4,5)
    ACCUM(5,5)
    #pragma unroll
    for (int m = 0; m < NG; m++) {
        float g = 0.f;
        #pragma unroll
        for (int r = 0; r < NG; r++) g = fmaf(h[r], c_cheb[r][m], g);
        g_gcoef[(size_t)t * NG + m] = g;
    }
}

// ---- packed fp32x2 helpers (sm_100+) ----
typedef unsigned long long u64t;

__device__ __forceinline__ u64t pk2(float lo, float hi) {
    u64t r; asm("mov.b64 %0, {%1,%2};" : "=l"(r) : "f"(lo), "f"(hi)); return r;
}
__device__ __forceinline__ void upk2(u64t v, float& lo, float& hi) {
    asm("mov.b64 {%0,%1}, %2;" : "=f"(lo), "=f"(hi) : "l"(v));
}
__device__ __forceinline__ u64t fma2(u64t a, u64t b, u64t c) {
    u64t d; asm("fma.rn.f32x2 %0, %1, %2, %3;" : "=l"(d) : "l"(a), "l"(b), "l"(c)); return d;
}
__device__ __forceinline__ u64t add2(u64t a, u64t b) {
    u64t d; asm("add.rn.f32x2 %0, %1, %2;" : "=l"(d) : "l"(a), "l"(b)); return d;
}

// One CTA per (b,c,u,v) segment. 256 threads, 16 px/thread in regs.
// G coeffs loaded up-front (latency overlapped with min/max pass).
__global__ __launch_bounds__(256, 4) void cft_main_kernel(const float* __restrict__ x,
                                                          float* __restrict__ out) {
    int seg = blockIdx.x;              // ((b*64+c)*4+u)*4+v
    int v = seg & 3;
    int u = (seg >> 2) & 3;
    int bc = seg >> 4;
    int c = bc & 63;
    size_t base = (size_t)bc * (HH * WW) + (size_t)u * HS * WW + (size_t)v * WS;
    const float4* __restrict__ xin = (const float4*)(x + base);
    int tid = threadIdx.x;
    int lane = tid & 31, warp = tid >> 5;

    float4 d[4];
    #pragma unroll
    for (int it = 0; it < 4; it++) {
        int q = it * 256 + tid;
        d[it] = xin[(q >> 4) * (WW / 4) + (q & 15)];
    }

    // Issue the 12 coefficient loads NOW so their latency overlaps the min/max.
    const float* __restrict__ gp = g_gcoef + ((size_t)((u * NS + v) * NC) + c) * NG;
    float gs[NG];
    #pragma unroll
    for (int m = 0; m < NG; m++) gs[m] = __ldg(gp + m);

    // ---- pass 1: per-segment min/max ----
    float mn = d[0].x, mx = d[0].x;
    #pragma unroll
    for (int it = 0; it < 4; it++) {
        mn = fminf(mn, fminf(fminf(d[it].x, d[it].y), fminf(d[it].z, d[it].w)));
        mx = fmaxf(mx, fmaxf(fmaxf(d[it].x, d[it].y), fmaxf(d[it].z, d[it].w)));
    }
    #pragma unroll
    for (int off = 16; off; off >>= 1) {
        mn = fminf(mn, __shfl_xor_sync(0xffffffffu, mn, off));
        mx = fmaxf(mx, __shfl_xor_sync(0xffffffffu, mx, off));
    }
    __shared__ float s_mn[8], s_mx[8];
    __shared__ float s_part[8];
    if (lane == 0) { s_mn[warp] = mn; s_mx[warp] = mx; }
    __syncthreads();
    mn = s_mn[0]; mx = s_mx[0];
    #pragma unroll
    for (int k = 1; k < 8; k++) { mn = fminf(mn, s_mn[k]); mx = fmaxf(mx, s_mx[k]); }

    // ---- pass 2: packed Horner accumulation ----
    float a = 2.0f / (mx - mn + 1e-8f);
    float bb = fmaf(-mn, a, -1.0f);        // xn = x*a + bb
    u64t a2 = pk2(a, a);
    u64t b2 = pk2(bb, bb);
    u64t G[NG];
    #pragma unroll
    for (int m = 0; m < NG; m++) G[m] = pk2(gs[m], gs[m]);

    u64t acc = 0ull;   // {+0.0f,+0.0f}
    #pragma unroll
    for (int it = 0; it < 4; it++) {
        #pragma unroll
        for (int half = 0; half < 2; half++) {
            u64t val2 = half ? pk2(d[it].z, d[it].w) : pk2(d[it].x, d[it].y);
            u64t xn = fma2(val2, a2, b2);
            u64t p = G[11];
            #pragma unroll
            for (int m = 10; m >= 0; m--) p = fma2(p, xn, G[m]);
            acc = add2(acc, p);
        }
    }

    // ---- reduce one scalar across block; all threads finish redundantly ----
    float lo, hi; upk2(acc, lo, hi);
    float part = lo + hi;
    #pragma unroll
    for (int off = 16; off; off >>= 1)
        part += __shfl_xor_sync(0xffffffffu, part, off);
    if (lane == 0) s_part[warp] = part;
    __syncthreads();
    float s = s_part[0];
    #pragma unroll
    for (int k = 1; k < 8; k++) s += s_part[k];
    float sig = tanhf(s);

    // ---- broadcast-store the segment ----
    float4 o4 = make_float4(sig, sig, sig, sig);
    float4* oo = (float4*)(out + base);
    #pragma unroll
    for (int it = 0; it < 4; it++) {
        int q = it * 256 + tid;
        oo[(q >> 4) * (WW / 4) + (q & 15)] = o4;
    }
}

extern "C" void kernel_launch(void* const* d_in, const int* in_sizes, int n_in,
                              void* d_out, int out_size) {
    const float* x = (const float*)d_in[0];
    const float* w = (const float*)d_in[1];
    float* out = (float*)d_out;
    prep_rowsum_kernel<<<NROWS / 8, 256>>>(w);
    prep_transform_kernel<<<4, 256>>>();
    cft_main_kernel<<<NB * NC * NS * NS, 256>>>(x, out);
}

// round 8
// speedup vs baseline: 1.4052x; 1.0108x over previous
#include <cuda_runtime.h>

#define NB 4
#define NC 64
#define NS 4
#define NM 6
#define NP 21
#define HS 64
#define WS 64
#define HH 256
#define WW 256
#define NG 12
#define NROWS (NS * NS * NM * NM * NC)   // 36864 rows of 64 floats

// Per-row means of w over C_OUT (incl. 1/64/4096): g_wsum[uv][i][j][c]
__device__ float g_wsum[NROWS];
// Final per-(u,v,c) monomial coefficients g[0..11]: part = sum_px sum_m g_m xn^m
__device__ float g_gcoef[NS * NS * NC * NG];

// Monomial coefficients of Chebyshev T_r (row r, column m)
__constant__ float c_cheb[NG][NG] = {
  {1,0,0,0,0,0,0,0,0,0,0,0},
  {0,1,0,0,0,0,0,0,0,0,0,0},
  {-1,0,2,0,0,0,0,0,0,0,0,0},
  {0,-3,0,4,0,0,0,0,0,0,0,0},
  {1,0,-8,0,8,0,0,0,0,0,0,0},
  {0,5,0,-20,0,16,0,0,0,0,0,0},
  {-1,0,18,0,-48,0,32,0,0,0,0,0},
  {0,-7,0,56,0,-112,0,64,0,0,0,0},
  {1,0,-32,0,160,0,-256,0,128,0,0,0},
  {0,9,0,-120,0,432,0,-576,0,256,0,0},
  {-1,0,50,0,-400,0,1120,0,-1280,0,512,0},
  {0,-11,0,220,0,-1232,0,2816,0,-2816,0,1024}
};

// grid = 144 blocks x 256: ONE THREAD per 64-float row. 16 independent float4
// loads (MLP=16) fully hide DRAM latency; pure register tree-sum, no shuffles.
__global__ void prep_rowsum_kernel(const float* __restrict__ w) {
    int r = blockIdx.x * 256 + threadIdx.x;   // 0..36863
    const float4* __restrict__ row = (const float4*)(w + (size_t)r * 64);
    float4 v[16];
    #pragma unroll
    for (int i = 0; i < 16; i++) v[i] = __ldg(row + i);
    float s4x = 0.f, s4y = 0.f, s4z = 0.f, s4w = 0.f;
    #pragma unroll
    for (int i = 0; i < 16; i++) {
        s4x += v[i].x; s4y += v[i].y; s4z += v[i].z; s4w += v[i].w;
    }
    g_wsum[r] = ((s4x + s4y) + (s4z + s4w)) * (1.0f / (64.0f * 4096.0f));
}

// 1024 threads: per (uv,c), fold symmetric pairs, expand x*Ti*Tj into Chebyshev
// basis (x*Ti*Tj = (T_{i+j+1}+T_{|i+j-1|}+T_{j-i+1}+T_{|j-i-1|})/4), then
// convert to monomial coefficients g[0..11].
#define ABSI(x) ((x) < 0 ? -(x) : (x))
#define ACCUM(i, j) { float wv = g_wsum[((uv * 36 + (i) * 6 + (j)) << 6) + c];   \
    if ((i) != (j)) wv += g_wsum[((uv * 36 + (j) * 6 + (i)) << 6) + c];          \
    wv *= 0.25f;                                                                  \
    h[(i)+(j)+1] += wv; h[ABSI((i)+(j)-1)] += wv;                                 \
    h[(j)-(i)+1] += wv; h[ABSI((j)-(i)-1)] += wv; }

__global__ void prep_transform_kernel() {
    int t = blockIdx.x * 256 + threadIdx.x;   // 0..1023 = (uv*64+c)
    if (t >= NS * NS * NC) return;
    int uv = t >> 6;
    int c = t & 63;
    float h[NG];
    #pragma unroll
    for (int r = 0; r < NG; r++) h[r] = 0.f;
    ACCUM(0,0) ACCUM(0,1) ACCUM(0,2) ACCUM(0,3) ACCUM(0,4) ACCUM(0,5)
    ACCUM(1,1) ACCUM(1,2) ACCUM(1,3) ACCUM(1,4) ACCUM(1,5)
    ACCUM(2,2) ACCUM(2,3) ACCUM(2,4) ACCUM(2,5)
    ACCUM(3,3) ACCUM(3,4) ACCUM(3,5)
    ACCUM(4,4) ACCUM(4,5)
    ACCUM(5,5)
    #pragma unroll
    for (int m = 0; m < NG; m++) {
        float g = 0.f;
        #pragma unroll
        for (int r = 0; r < NG; r++) g = fmaf(h[r], c_cheb[r][m], g);
        g_gcoef[(size_t)t * NG + m] = g;
    }
}

// ---- packed fp32x2 helpers (sm_100+) ----
typedef unsigned long long u64t;

__device__ __forceinline__ u64t pk2(float lo, float hi) {
    u64t r; asm("mov.b64 %0, {%1,%2};" : "=l"(r) : "f"(lo), "f"(hi)); return r;
}
__device__ __forceinline__ void upk2(u64t v, float& lo, float& hi) {
    asm("mov.b64 {%0,%1}, %2;" : "=f"(lo), "=f"(hi) : "l"(v));
}
__device__ __forceinline__ u64t fma2(u64t a, u64t b, u64t c) {
    u64t d; asm("fma.rn.f32x2 %0, %1, %2, %3;" : "=l"(d) : "l"(a), "l"(b), "l"(c)); return d;
}
__device__ __forceinline__ u64t add2(u64t a, u64t b) {
    u64t d; asm("add.rn.f32x2 %0, %1, %2;" : "=l"(d) : "l"(a), "l"(b)); return d;
}

// One CTA per (b,c,u,v) segment. 256 threads, 16 px/thread in regs.
// G coeffs loaded up-front (latency overlapped with min/max pass).
__global__ __launch_bounds__(256, 4) void cft_main_kernel(const float* __restrict__ x,
                                                          float* __restrict__ out) {
    int seg = blockIdx.x;              // ((b*64+c)*4+u)*4+v
    int v = seg & 3;
    int u = (seg >> 2) & 3;
    int bc = seg >> 4;
    int c = bc & 63;
    size_t base = (size_t)bc * (HH * WW) + (size_t)u * HS * WW + (size_t)v * WS;
    const float4* __restrict__ xin = (const float4*)(x + base);
    int tid = threadIdx.x;
    int lane = tid & 31, warp = tid >> 5;

    float4 d[4];
    #pragma unroll
    for (int it = 0; it < 4; it++) {
        int q = it * 256 + tid;
        d[it] = xin[(q >> 4) * (WW / 4) + (q & 15)];
    }

    // Issue the 12 coefficient loads NOW so their latency overlaps the min/max.
    const float* __restrict__ gp = g_gcoef + ((size_t)((u * NS + v) * NC) + c) * NG;
    float gs[NG];
    #pragma unroll
    for (int m = 0; m < NG; m++) gs[m] = __ldg(gp + m);

    // ---- pass 1: per-segment min/max ----
    float mn = d[0].x, mx = d[0].x;
    #pragma unroll
    for (int it = 0; it < 4; it++) {
        mn = fminf(mn, fminf(fminf(d[it].x, d[it].y), fminf(d[it].z, d[it].w)));
        mx = fmaxf(mx, fmaxf(fmaxf(d[it].x, d[it].y), fmaxf(d[it].z, d[it].w)));
    }
    #pragma unroll
    for (int off = 16; off; off >>= 1) {
        mn = fminf(mn, __shfl_xor_sync(0xffffffffu, mn, off));
        mx = fmaxf(mx, __shfl_xor_sync(0xffffffffu, mx, off));
    }
    __shared__ float s_mn[8], s_mx[8];
    __shared__ float s_part[8];
    if (lane == 0) { s_mn[warp] = mn; s_mx[warp] = mx; }
    __syncthreads();
    mn = s_mn[0]; mx = s_mx[0];
    #pragma unroll
    for (int k = 1; k < 8; k++) { mn = fminf(mn, s_mn[k]); mx = fmaxf(mx, s_mx[k]); }

    // ---- pass 2: packed Horner accumulation ----
    float a = 2.0f / (mx - mn + 1e-8f);
    float bb = fmaf(-mn, a, -1.0f);        // xn = x*a + bb
    u64t a2 = pk2(a, a);
    u64t b2 = pk2(bb, bb);
    u64t G[NG];
    #pragma unroll
    for (int m = 0; m < NG; m++) G[m] = pk2(gs[m], gs[m]);

    u64t acc = 0ull;   // {+0.0f,+0.0f}
    #pragma unroll
    for (int it = 0; it < 4; it++) {
        #pragma unroll
        for (int half = 0; half < 2; half++) {
            u64t val2 = half ? pk2(d[it].z, d[it].w) : pk2(d[it].x, d[it].y);
            u64t xn = fma2(val2, a2, b2);
            u64t p = G[11];
            #pragma unroll
            for (int m = 10; m >= 0; m--) p = fma2(p, xn, G[m]);
            acc = add2(acc, p);
        }
    }

    // ---- reduce one scalar across block; all threads finish redundantly ----
    float lo, hi; upk2(acc, lo, hi);
    float part = lo + hi;
    #pragma unroll
    for (int off = 16; off; off >>= 1)
        part += __shfl_xor_sync(0xffffffffu, part, off);
    if (lane == 0) s_part[warp] = part;
    __syncthreads();
    float s = s_part[0];
    #pragma unroll
    for (int k = 1; k < 8; k++) s += s_part[k];
    float sig = tanhf(s);

    // ---- broadcast-store the segment ----
    float4 o4 = make_float4(sig, sig, sig, sig);
    float4* oo = (float4*)(out + base);
    #pragma unroll
    for (int it = 0; it < 4; it++) {
        int q = it * 256 + tid;
        oo[(q >> 4) * (WW / 4) + (q & 15)] = o4;
    }
}

extern "C" void kernel_launch(void* const* d_in, const int* in_sizes, int n_in,
                              void* d_out, int out_size) {
    const float* x = (const float*)d_in[0];
    const float* w = (const float*)d_in[1];
    float* out = (float*)d_out;
    prep_rowsum_kernel<<<NROWS / 256, 256>>>(w);
    prep_transform_kernel<<<4, 256>>>();
    cft_main_kernel<<<NB * NC * NS * NS, 256>>>(x, out);
}

// round 9
// speedup vs baseline: 1.5369x; 1.0937x over previous
#include <cuda_runtime.h>

#define NB 4
#define NC 64
#define NS 4
#define NM 6
#define NP 21
#define HS 64
#define WS 64
#define HH 256
#define WW 256
#define NG 12
#define NROWS (NS * NS * NM * NM * NC)   // 36864 rows of 64 floats

// Per-row means of w over C_OUT (incl. 1/64/4096): g_wsum[uv][i][j][c]
__device__ float g_wsum[NROWS];
// Final per-(u,v,c) monomial coefficients g[0..11]: part = sum_px sum_m g_m xn^m
__device__ float g_gcoef[NS * NS * NC * NG];

// Monomial coefficients of Chebyshev T_r (row r, column m)
__constant__ float c_cheb[NG][NG] = {
  {1,0,0,0,0,0,0,0,0,0,0,0},
  {0,1,0,0,0,0,0,0,0,0,0,0},
  {-1,0,2,0,0,0,0,0,0,0,0,0},
  {0,-3,0,4,0,0,0,0,0,0,0,0},
  {1,0,-8,0,8,0,0,0,0,0,0,0},
  {0,5,0,-20,0,16,0,0,0,0,0,0},
  {-1,0,18,0,-48,0,32,0,0,0,0,0},
  {0,-7,0,56,0,-112,0,64,0,0,0,0},
  {1,0,-32,0,160,0,-256,0,128,0,0,0},
  {0,9,0,-120,0,432,0,-576,0,256,0,0},
  {-1,0,50,0,-400,0,1120,0,-1280,0,512,0},
  {0,-11,0,220,0,-1232,0,2816,0,-2816,0,1024}
};

// grid = 576 blocks x 256: QUARTER-ROW (4 float4) per thread; 4 lanes/row.
// 147k threads x 4 independent LDG.128 saturates DRAM; 2-shuffle finish.
__global__ void prep_rowsum_kernel(const float* __restrict__ w) {
    int t = blockIdx.x * 256 + threadIdx.x;   // 0..147455
    int r = t >> 2;                           // row 0..36863
    int q = t & 3;                            // quarter within row
    const float4* __restrict__ p = (const float4*)w + (size_t)r * 16 + q * 4;
    float4 v0 = __ldcs(p + 0);
    float4 v1 = __ldcs(p + 1);
    float4 v2 = __ldcs(p + 2);
    float4 v3 = __ldcs(p + 3);
    float s = ((v0.x + v0.y) + (v0.z + v0.w)) + ((v1.x + v1.y) + (v1.z + v1.w))
            + ((v2.x + v2.y) + (v2.z + v2.w)) + ((v3.x + v3.y) + (v3.z + v3.w));
    s += __shfl_xor_sync(0xffffffffu, s, 2);
    s += __shfl_xor_sync(0xffffffffu, s, 1);
    if (q == 0)
        g_wsum[r] = s * (1.0f / (64.0f * 4096.0f));
}

// 1024 threads: per (uv,c), fold symmetric pairs, expand x*Ti*Tj into Chebyshev
// basis (x*Ti*Tj = (T_{i+j+1}+T_{|i+j-1|}+T_{j-i+1}+T_{|j-i-1|})/4), then
// convert to monomial coefficients g[0..11].
#define ABSI(x) ((x) < 0 ? -(x) : (x))
#define ACCUM(i, j) { float wv = g_wsum[((uv * 36 + (i) * 6 + (j)) << 6) + c];   \
    if ((i) != (j)) wv += g_wsum[((uv * 36 + (j) * 6 + (i)) << 6) + c];          \
    wv *= 0.25f;                                                                  \
    h[(i)+(j)+1] += wv; h[ABSI((i)+(j)-1)] += wv;                                 \
    h[(j)-(i)+1] += wv; h[ABSI((j)-(i)-1)] += wv; }

__global__ void prep_transform_kernel() {
    int t = blockIdx.x * 256 + threadIdx.x;   // 0..1023 = (uv*64+c)
    if (t >= NS * NS * NC) return;
    int uv = t >> 6;
    int c = t & 63;
    float h[NG];
    #pragma unroll
    for (int r = 0; r < NG; r++) h[r] = 0.f;
    ACCUM(0,0) ACCUM(0,1) ACCUM(0,2) ACCUM(0,3) ACCUM(0,4) ACCUM(0,5)
    ACCUM(1,1) ACCUM(1,2) ACCUM(1,3) ACCUM(1,4) ACCUM(1,5)
    ACCUM(2,2) ACCUM(2,3) ACCUM(2,4) ACCUM(2,5)
    ACCUM(3,3) ACCUM(3,4) ACCUM(3,5)
    ACCUM(4,4) ACCUM(4,5)
    ACCUM(5,5)
    #pragma unroll
    for (int m = 0; m < NG; m++) {
        float g = 0.f;
        #pragma unroll
        for (int r = 0; r < NG; r++) g = fmaf(h[r], c_cheb[r][m], g);
        g_gcoef[(size_t)t * NG + m] = g;
    }
}

// ---- packed fp32x2 helpers (sm_100+) ----
typedef unsigned long long u64t;

__device__ __forceinline__ u64t pk2(float lo, float hi) {
    u64t r; asm("mov.b64 %0, {%1,%2};" : "=l"(r) : "f"(lo), "f"(hi)); return r;
}
__device__ __forceinline__ void upk2(u64t v, float& lo, float& hi) {
    asm("mov.b64 {%0,%1}, %2;" : "=f"(lo), "=f"(hi) : "l"(v));
}
__device__ __forceinline__ u64t fma2(u64t a, u64t b, u64t c) {
    u64t d; asm("fma.rn.f32x2 %0, %1, %2, %3;" : "=l"(d) : "l"(a), "l"(b), "l"(c)); return d;
}
__device__ __forceinline__ u64t add2(u64t a, u64t b) {
    u64t d; asm("add.rn.f32x2 %0, %1, %2;" : "=l"(d) : "l"(a), "l"(b)); return d;
}

// One CTA per (b,c,u,v) segment. 256 threads, 16 px/thread in regs.
// Streaming loads/stores (data touched exactly once); G coeffs prefetched.
__global__ __launch_bounds__(256, 4) void cft_main_kernel(const float* __restrict__ x,
                                                          float* __restrict__ out) {
    int seg = blockIdx.x;              // ((b*64+c)*4+u)*4+v
    int v = seg & 3;
    int u = (seg >> 2) & 3;
    int bc = seg >> 4;
    int c = bc & 63;
    size_t base = (size_t)bc * (HH * WW) + (size_t)u * HS * WW + (size_t)v * WS;
    const float4* __restrict__ xin = (const float4*)(x + base);
    int tid = threadIdx.x;
    int lane = tid & 31, warp = tid >> 5;

    float4 d[4];
    #pragma unroll
    for (int it = 0; it < 4; it++) {
        int q = it * 256 + tid;
        d[it] = __ldcs(xin + (q >> 4) * (WW / 4) + (q & 15));
    }

    // Issue the 12 coefficient loads NOW so their latency overlaps the min/max.
    const float* __restrict__ gp = g_gcoef + ((size_t)((u * NS + v) * NC) + c) * NG;
    float gs[NG];
    #pragma unroll
    for (int m = 0; m < NG; m++) gs[m] = __ldg(gp + m);

    // ---- pass 1: per-segment min/max ----
    float mn = d[0].x, mx = d[0].x;
    #pragma unroll
    for (int it = 0; it < 4; it++) {
        mn = fminf(mn, fminf(fminf(d[it].x, d[it].y), fminf(d[it].z, d[it].w)));
        mx = fmaxf(mx, fmaxf(fmaxf(d[it].x, d[it].y), fmaxf(d[it].z, d[it].w)));
    }
    #pragma unroll
    for (int off = 16; off; off >>= 1) {
        mn = fminf(mn, __shfl_xor_sync(0xffffffffu, mn, off));
        mx = fmaxf(mx, __shfl_xor_sync(0xffffffffu, mx, off));
    }
    __shared__ float s_mn[8], s_mx[8];
    __shared__ float s_part[8];
    if (lane == 0) { s_mn[warp] = mn; s_mx[warp] = mx; }
    __syncthreads();
    mn = s_mn[0]; mx = s_mx[0];
    #pragma unroll
    for (int k = 1; k < 8; k++) { mn = fminf(mn, s_mn[k]); mx = fmaxf(mx, s_mx[k]); }

    // ---- pass 2: packed Horner accumulation ----
    float a = 2.0f / (mx - mn + 1e-8f);
    float bb = fmaf(-mn, a, -1.0f);        // xn = x*a + bb
    u64t a2 = pk2(a, a);
    u64t b2 = pk2(bb, bb);
    u64t G[NG];
    #pragma unroll
    for (int m = 0; m < NG; m++) G[m] = pk2(gs[m], gs[m]);

    u64t acc = 0ull;   // {+0.0f,+0.0f}
    #pragma unroll
    for (int it = 0; it < 4; it++) {
        #pragma unroll
        for (int half = 0; half < 2; half++) {
            u64t val2 = half ? pk2(d[it].z, d[it].w) : pk2(d[it].x, d[it].y);
            u64t xn = fma2(val2, a2, b2);
            u64t p = G[11];
            #pragma unroll
            for (int m = 10; m >= 0; m--) p = fma2(p, xn, G[m]);
            acc = add2(acc, p);
        }
    }

    // ---- reduce one scalar across block; all threads finish redundantly ----
    float lo, hi; upk2(acc, lo, hi);
    float part = lo + hi;
    #pragma unroll
    for (int off = 16; off; off >>= 1)
        part += __shfl_xor_sync(0xffffffffu, part, off);
    if (lane == 0) s_part[warp] = part;
    __syncthreads();
    float s = s_part[0];
    #pragma unroll
    for (int k = 1; k < 8; k++) s += s_part[k];
    float sig = tanhf(s);

    // ---- broadcast-store the segment (streaming stores) ----
    float4 o4 = make_float4(sig, sig, sig, sig);
    float4* oo = (float4*)(out + base);
    #pragma unroll
    for (int it = 0; it < 4; it++) {
        int q = it * 256 + tid;
        __stcs(oo + (q >> 4) * (WW / 4) + (q & 15), o4);
    }
}

extern "C" void kernel_launch(void* const* d_in, const int* in_sizes, int n_in,
                              void* d_out, int out_size) {
    const float* x = (const float*)d_in[0];
    const float* w = (const float*)d_in[1];
    float* out = (float*)d_out;
    prep_rowsum_kernel<<<NROWS * 4 / 256, 256>>>(w);
    prep_transform_kernel<<<4, 256>>>();
    cft_main_kernel<<<NB * NC * NS * NS, 256>>>(x, out);
}